// round 9
// baseline (speedup 1.0000x reference)
#include <cuda_runtime.h>
#include <cuda_fp16.h>
#include <cstdint>

#define TOK   4096
#define EMB   512
#define QKVN  1536
#define HEADS 8
#define DH    64
#define SCALE 0.125f

#define HSTRIDE (TOK * DH)           // 262144
#define PSTRIDE (HEADS * TOK * DH)   // 2097152

// ---------------- scratch (device globals) ----------------
__device__ float g_qkv[3 * HEADS * TOK * DH];        // [part][h][n][d]
__device__ float g_qsum[HEADS * DH];
__device__ float g_qsum_part[32 * HEADS * DH];       // [m_block][h*64+d]
__device__ float g_ktv[HEADS * DH * DH];
__device__ float g_ktv_part[32 * HEADS * DH * DH];

__device__ __half g_a_hi[TOK * EMB];                 // A = x^T  [4096, 512]
__device__ __half g_b_hi[QKVN * EMB];                // B = W^T  [1536, 512]

// ---------------- helpers ----------------
__device__ __forceinline__ uint32_t smem_u32(const void* p) {
    uint32_t a;
    asm("{ .reg .u64 t; cvta.to.shared.u64 t, %1; cvt.u32.u64 %0, t; }" : "=r"(a) : "l"(p));
    return a;
}
__device__ __forceinline__ uint32_t lds32(uint32_t a) {
    uint32_t v;
    asm volatile("ld.shared.b32 %0, [%1];" : "=r"(v) : "r"(a));
    return v;
}
__device__ __forceinline__ void cp_async16(uint32_t saddr, const void* gaddr) {
    asm volatile("cp.async.cg.shared.global [%0], [%1], 16;" :: "r"(saddr), "l"(gaddr));
}
__device__ __forceinline__ void cp_commit() { asm volatile("cp.async.commit_group;"); }
__device__ __forceinline__ void cp_wait1()  { asm volatile("cp.async.wait_group 1;"); }
__device__ __forceinline__ void cp_wait0()  { asm volatile("cp.async.wait_group 0;"); }

__device__ __forceinline__ void mma_f16(float& c0, float& c1, float& c2, float& c3,
                                        uint32_t a0, uint32_t a1, uint32_t a2, uint32_t a3,
                                        uint32_t b0, uint32_t b1) {
    asm volatile(
        "mma.sync.aligned.m16n8k16.row.col.f32.f16.f16.f32 "
        "{%0,%1,%2,%3}, {%4,%5,%6,%7}, {%8,%9}, {%0,%1,%2,%3};"
        : "+f"(c0), "+f"(c1), "+f"(c2), "+f"(c3)
        : "r"(a0), "r"(a1), "r"(a2), "r"(a3), "r"(b0), "r"(b1));
}

// packed fp32x2 (Blackwell FFMA2 path, exact fp32 semantics)
__device__ __forceinline__ unsigned long long dup2(float x) {
    unsigned long long r;
    asm("mov.b64 %0, {%1, %1};" : "=l"(r) : "f"(x));
    return r;
}
__device__ __forceinline__ unsigned long long fma2(unsigned long long a,
                                                   unsigned long long b,
                                                   unsigned long long c) {
    unsigned long long d;
    asm("fma.rn.f32x2 %0, %1, %2, %3;" : "=l"(d) : "l"(a), "l"(b), "l"(c));
    return d;
}
__device__ __forceinline__ void unpack2(unsigned long long v, float& x, float& y) {
    asm("mov.b64 {%0, %1}, %2;" : "=f"(x), "=f"(y) : "l"(v));
}
__device__ __forceinline__ void lds_v2u64(uint32_t addr, unsigned long long& a,
                                          unsigned long long& b) {
    asm volatile("ld.shared.v2.u64 {%0, %1}, [%2];" : "=l"(a), "=l"(b) : "r"(addr));
}

// ---------------------------------------------------------------------------
// Pre-pass: transpose src[512, Mcols] f32 -> dhi [Mcols, 512] fp16
// ---------------------------------------------------------------------------
__global__ __launch_bounds__(256) void conv_transpose(const float* __restrict__ src,
                                                      __half* __restrict__ dhi,
                                                      int Mcols) {
    __shared__ float tile[32][33];
    int tx = threadIdx.x & 31, ty = threadIdx.x >> 5;
    int m0 = blockIdx.x * 32, k0 = blockIdx.y * 32;
#pragma unroll
    for (int j = 0; j < 4; j++)
        tile[ty + j * 8][tx] = src[(size_t)(k0 + ty + j * 8) * Mcols + m0 + tx];
    __syncthreads();
#pragma unroll
    for (int j = 0; j < 4; j++) {
        int m = m0 + ty + j * 8;
        dhi[(size_t)m * EMB + k0 + tx] = __float2half_rn(tile[tx][ty + j * 8]);
    }
}

// ---------------------------------------------------------------------------
// mma.sync QKV GEMM (round-7, unchanged)
// ---------------------------------------------------------------------------
#define GBM 128
#define GBN 128
#define GBK 32
#define ROWB   80
#define TILE_B (128 * ROWB)
#define T_AHI  0
#define T_BHI  (1 * TILE_B)
#define STG_B  (2 * TILE_B)
#define SM_BIAS (2 * STG_B)
#define SM_QS   (SM_BIAS + 512)
#define SM_TOT  (SM_QS + 1024)

__global__ void __launch_bounds__(256, 2) qkv_gemm_mma(const float* __restrict__ bias) {
    extern __shared__ char smem[];
    const uint32_t sb = smem_u32(smem);
    const int tid  = threadIdx.x;
    const int wid  = tid >> 5;
    const int lane = tid & 31;
    const int g    = lane >> 2;
    const int tg   = lane & 3;
    const int wm   = wid >> 2;
    const int wn   = wid & 3;
    const int o0   = blockIdx.x * GBN;
    const int m0   = blockIdx.y * GBM;

    if (tid < 128) *reinterpret_cast<float*>(smem + SM_BIAS + tid * 4) = bias[o0 + tid];

    const __half* srcs[2] = {
        &g_a_hi[(size_t)m0 * EMB], &g_b_hi[(size_t)o0 * EMB]};

    auto issue = [&](int chunk) {
        const int kt = chunk * GBK;
        const uint32_t stage = sb + (chunk & 1) * STG_B;
#pragma unroll
        for (int t = 0; t < 2; t++) {
            const __half* gp = srcs[t] + kt;
            const uint32_t tb = stage + t * TILE_B;
#pragma unroll
            for (int i = 0; i < 2; i++) {
                int lin = tid + i * 256;
                int row = lin >> 2;
                int seg = lin & 3;
                cp_async16(tb + row * ROWB + seg * 16, gp + (size_t)row * EMB + seg * 8);
            }
        }
        cp_commit();
    };

    float acc[4][4][4];
#pragma unroll
    for (int i = 0; i < 4; i++)
#pragma unroll
        for (int j = 0; j < 4; j++)
#pragma unroll
            for (int c = 0; c < 4; c++) acc[i][j][c] = 0.f;

    issue(0);

    const uint32_t aRow0 = wm * 64 + g;
    const uint32_t bRow0 = wn * 32 + g;

    for (int chunk = 0; chunk < EMB / GBK; ++chunk) {
        if (chunk + 1 < EMB / GBK) { issue(chunk + 1); cp_wait1(); }
        else                       { cp_wait0(); }
        __syncthreads();

        const uint32_t stage = sb + (chunk & 1) * STG_B;

#pragma unroll
        for (int kk = 0; kk < 2; kk++) {
            const uint32_t klo = kk * 32 + tg * 4;

            uint32_t afr[4][4], bfr[4][2];
#pragma unroll
            for (int nt = 0; nt < 4; nt++) {
                uint32_t base = stage + (bRow0 + nt * 8) * ROWB + klo + T_BHI;
                bfr[nt][0] = lds32(base);
                bfr[nt][1] = lds32(base + 16);
            }
#pragma unroll
            for (int mt = 0; mt < 4; mt++) {
                uint32_t base = stage + (aRow0 + mt * 16) * ROWB + klo + T_AHI;
                afr[mt][0] = lds32(base);
                afr[mt][1] = lds32(base + 8 * ROWB);
                afr[mt][2] = lds32(base + 16);
                afr[mt][3] = lds32(base + 8 * ROWB + 16);
            }
#pragma unroll
            for (int mt = 0; mt < 4; mt++)
#pragma unroll
                for (int nt = 0; nt < 4; nt++)
                    mma_f16(acc[mt][nt][0], acc[mt][nt][1], acc[mt][nt][2], acc[mt][nt][3],
                            afr[mt][0], afr[mt][1], afr[mt][2], afr[mt][3],
                            bfr[nt][0], bfr[nt][1]);
        }
        __syncthreads();
    }

    const float* sbias = reinterpret_cast<const float*>(smem + SM_BIAS);
#pragma unroll
    for (int mt = 0; mt < 4; mt++) {
        const int m = m0 + wm * 64 + mt * 16 + g;
#pragma unroll
        for (int nt = 0; nt < 4; nt++) {
            const int off = wn * 32 + nt * 8 + 2 * tg;
            const int o = o0 + off;
            const int part = o >> 9;
            const int h = (o >> 6) & 7;
            const int d = o & 63;
            const float bv0 = sbias[off], bv1 = sbias[off + 1];
            float* base = &g_qkv[(size_t)part * PSTRIDE + (size_t)h * HSTRIDE];
            float2 r0 = {acc[mt][nt][0] + bv0, acc[mt][nt][1] + bv1};
            float2 r1 = {acc[mt][nt][2] + bv0, acc[mt][nt][3] + bv1};
            *reinterpret_cast<float2*>(&base[(size_t)m * DH + d]) = r0;
            *reinterpret_cast<float2*>(&base[(size_t)(m + 8) * DH + d]) = r1;
        }
    }

    // fused qsum partial
    if (o0 < 512) {
        float* qs = reinterpret_cast<float*>(smem + SM_QS);
        float cs[8];
#pragma unroll
        for (int nt = 0; nt < 4; nt++)
#pragma unroll
            for (int j = 0; j < 2; j++) {
                const int off = wn * 32 + nt * 8 + 2 * tg + j;
                float s = 8.f * sbias[off];
#pragma unroll
                for (int mt = 0; mt < 4; mt++)
                    s += acc[mt][nt][j] + acc[mt][nt][j + 2];
                cs[nt * 2 + j] = s;
            }
#pragma unroll
        for (int i = 0; i < 8; i++) {
#pragma unroll
            for (int off = 4; off < 32; off <<= 1)
                cs[i] += __shfl_xor_sync(0xffffffffu, cs[i], off);
        }
        if (g == 0) {
#pragma unroll
            for (int nt = 0; nt < 4; nt++)
#pragma unroll
                for (int j = 0; j < 2; j++)
                    qs[wm * 128 + wn * 32 + nt * 8 + 2 * tg + j] = cs[nt * 2 + j];
        }
        __syncthreads();
        if (tid < 128)
            g_qsum_part[blockIdx.y * 512 + o0 + tid] = qs[tid] + qs[128 + tid];
    }
}

// ---------------------------------------------------------------------------
// partial KtV over 32 N-splits (round-7, unchanged)
// ---------------------------------------------------------------------------
__global__ __launch_bounds__(128) void ktv_kernel() {
    int h = blockIdx.x;
    int split = blockIdx.y;
    const float* Kp = &g_qkv[(size_t)1 * PSTRIDE + (size_t)h * HSTRIDE];
    const float* Vp = &g_qkv[(size_t)2 * PSTRIDE + (size_t)h * HSTRIDE];

    __shared__ float sK[32][64];
    __shared__ float sV[32][64];
    const uint32_t sVb = smem_u32(sV);

    int tid = threadIdx.x;
    int d1b = (tid >> 4) * 8;
    int d2b = (tid & 15) * 4;

    unsigned long long acc2[8][2];
#pragma unroll
    for (int i = 0; i < 8; i++) { acc2[i][0] = 0ull; acc2[i][1] = 0ull; }

    int nbase = split * 128;
    for (int nc = 0; nc < 128; nc += 32) {
#pragma unroll
        for (int i = 0; i < 4; i++) {
            int lin = tid + i * 128;
            int r = lin >> 4;
            int c = (lin & 15) << 2;
            *reinterpret_cast<float4*>(&sK[r][c]) =
                *reinterpret_cast<const float4*>(&Kp[(size_t)(nbase + nc + r) * DH + c]);
            *reinterpret_cast<float4*>(&sV[r][c]) =
                *reinterpret_cast<const float4*>(&Vp[(size_t)(nbase + nc + r) * DH + c]);
        }
        __syncthreads();
#pragma unroll
        for (int nn = 0; nn < 32; nn++) {
            float4 k0 = *reinterpret_cast<const float4*>(&sK[nn][d1b]);
            float4 k1 = *reinterpret_cast<const float4*>(&sK[nn][d1b + 4]);
            unsigned long long v01, v23;
            lds_v2u64(sVb + (nn * 64 + d2b) * 4, v01, v23);
            unsigned long long kd;
            kd = dup2(k0.x); acc2[0][0] = fma2(kd, v01, acc2[0][0]); acc2[0][1] = fma2(kd, v23, acc2[0][1]);
            kd = dup2(k0.y); acc2[1][0] = fma2(kd, v01, acc2[1][0]); acc2[1][1] = fma2(kd, v23, acc2[1][1]);
            kd = dup2(k0.z); acc2[2][0] = fma2(kd, v01, acc2[2][0]); acc2[2][1] = fma2(kd, v23, acc2[2][1]);
            kd = dup2(k0.w); acc2[3][0] = fma2(kd, v01, acc2[3][0]); acc2[3][1] = fma2(kd, v23, acc2[3][1]);
            kd = dup2(k1.x); acc2[4][0] = fma2(kd, v01, acc2[4][0]); acc2[4][1] = fma2(kd, v23, acc2[4][1]);
            kd = dup2(k1.y); acc2[5][0] = fma2(kd, v01, acc2[5][0]); acc2[5][1] = fma2(kd, v23, acc2[5][1]);
            kd = dup2(k1.z); acc2[6][0] = fma2(kd, v01, acc2[6][0]); acc2[6][1] = fma2(kd, v23, acc2[6][1]);
            kd = dup2(k1.w); acc2[7][0] = fma2(kd, v01, acc2[7][0]); acc2[7][1] = fma2(kd, v23, acc2[7][1]);
        }
        __syncthreads();
    }

    float* dst = &g_ktv_part[(size_t)split * (HEADS * DH * DH) + (size_t)h * DH * DH];
#pragma unroll
    for (int i = 0; i < 8; i++) {
        float4 v;
        unpack2(acc2[i][0], v.x, v.y);
        unpack2(acc2[i][1], v.z, v.w);
        *reinterpret_cast<float4*>(&dst[(d1b + i) * DH + d2b]) = v;
    }
}

// ktv reduce + fused qsum reduce (round-7, unchanged)
__global__ void ktv_reduce() {
    int i = blockIdx.x * 256 + threadIdx.x;
    float s = 0.f;
#pragma unroll
    for (int sp = 0; sp < 32; sp++) s += g_ktv_part[(size_t)sp * (HEADS * DH * DH) + i];
    g_ktv[i] = s;
    if (i < HEADS * DH) {
        float q = 0.f;
#pragma unroll
        for (int sp = 0; sp < 32; sp++) q += g_qsum_part[sp * (HEADS * DH) + i];
        g_qsum[i] = q;
    }
}

// ---------------------------------------------------------------------------
// out: 128 rows/block, 128 thr, 4 rows x 16 cols per thread, f32x2.
// M loads lane-rotated (conflict-free); Q padded-65 smem.
// ---------------------------------------------------------------------------
#define OQ_PAD 65
#define OSM_M   0                          // 64*64 floats = 16384 B
#define OSM_Q   16384                      // 128*65 floats = 33280 B
#define OSM_QS  (OSM_Q + 128 * OQ_PAD * 4) // 49664
#define OSM_TOT (OSM_QS + 256)             // 49920

__global__ void __launch_bounds__(128, 1) out_kernel(float* __restrict__ coarse,
                                                     float* __restrict__ out) {
    extern __shared__ char osm[];
    float* sM  = reinterpret_cast<float*>(osm + OSM_M);
    float* sQ  = reinterpret_cast<float*>(osm + OSM_Q);
    float* sQs = reinterpret_cast<float*>(osm + OSM_QS);
    const uint32_t sMb = smem_u32(sM);
    const uint32_t sQb = smem_u32(sQ);

    int h = blockIdx.x;
    int nt = blockIdx.y;
    int tid = threadIdx.x;

    // stage M: 1024 float4 / 128 thr
#pragma unroll
    for (int i = 0; i < 8; i++) {
        int lin = tid + i * 128;
        *reinterpret_cast<float4*>(&sM[lin * 4]) =
            *reinterpret_cast<const float4*>(&g_ktv[(size_t)h * DH * DH + lin * 4]);
    }
    if (tid < 64) sQs[tid] = g_qsum[h * 64 + tid];

    // stage Q tile [128 rows][64] padded to 65
    const float* Qg = &g_qkv[(size_t)h * HSTRIDE + (size_t)nt * 128 * DH];
#pragma unroll
    for (int i = 0; i < 16; i++) {
        int lin = tid + i * 128;           // 0..2047 float4s
        int r = lin >> 4;
        int c = (lin & 15) * 4;
        float4 v = *reinterpret_cast<const float4*>(&Qg[(size_t)r * DH + c]);
        float* dq = &sQ[r * OQ_PAD + c];
        dq[0] = v.x; dq[1] = v.y; dq[2] = v.z; dq[3] = v.w;
    }
    __syncthreads();

    // coarse: 1 row/thread (unchanged from r7)
    const int n = nt * 128 + tid;
    const float* Kr = &g_qkv[(size_t)1 * PSTRIDE + (size_t)h * HSTRIDE + (size_t)n * DH];
    float cacc = 0.f;
#pragma unroll
    for (int d4 = 0; d4 < 64; d4 += 4) {
        float4 k4 = *reinterpret_cast<const float4*>(&Kr[d4]);
        cacc += k4.x * sQs[d4] + k4.y * sQs[d4 + 1] + k4.z * sQs[d4 + 2] + k4.w * sQs[d4 + 3];
    }
    coarse[h * TOK + n] = cacc * SCALE;

    // main GEMV: rows rg*4..rg*4+3, cols cg..cg+15
    const int rg   = tid >> 2;             // 0..31
    const int lq   = tid & 3;              // lane quad id
    const int cg   = lq * 16;              // col base

    // rotated column-slot order (conflict-free across the lane quad)
    uint32_t coff[4];
#pragma unroll
    for (int c = 0; c < 4; c++) coff[c] = (uint32_t)(((c + lq) & 3) * 16);

    unsigned long long acc2[4][8];
#pragma unroll
    for (int j = 0; j < 4; j++)
#pragma unroll
        for (int p = 0; p < 8; p++) acc2[j][p] = 0ull;

    const uint32_t q0 = sQb + (rg * 4) * (OQ_PAD * 4);
    const uint32_t mc = sMb + cg * 4;

#pragma unroll 2
    for (int d1 = 0; d1 < 64; d1++) {
        unsigned long long qd0 = dup2(__uint_as_float(lds32(q0 + d1 * 4)));
        unsigned long long qd1 = dup2(__uint_as_float(lds32(q0 + OQ_PAD * 4 + d1 * 4)));
        unsigned long long qd2 = dup2(__uint_as_float(lds32(q0 + 2 * OQ_PAD * 4 + d1 * 4)));
        unsigned long long qd3 = dup2(__uint_as_float(lds32(q0 + 3 * OQ_PAD * 4 + d1 * 4)));
        const uint32_t mrow = mc + d1 * 256;
#pragma unroll
        for (int c = 0; c < 4; c++) {
            const uint32_t co = coff[c];
            unsigned long long m0, m1;
            lds_v2u64(mrow + co, m0, m1);
            const int p = (co >> 3);       // co/16*2 = slot pair index
            acc2[0][p]     = fma2(qd0, m0, acc2[0][p]);
            acc2[0][p + 1] = fma2(qd0, m1, acc2[0][p + 1]);
            acc2[1][p]     = fma2(qd1, m0, acc2[1][p]);
            acc2[1][p + 1] = fma2(qd1, m1, acc2[1][p + 1]);
            acc2[2][p]     = fma2(qd2, m0, acc2[2][p]);
            acc2[2][p + 1] = fma2(qd2, m1, acc2[2][p + 1]);
            acc2[3][p]     = fma2(qd3, m0, acc2[3][p]);
            acc2[3][p + 1] = fma2(qd3, m1, acc2[3][p + 1]);
        }
    }

#pragma unroll
    for (int j = 0; j < 4; j++) {
        const int nrow = nt * 128 + rg * 4 + j;
        float* op = &out[((size_t)h * TOK + nrow) * DH + cg];
#pragma unroll
        for (int c = 0; c < 4; c++) {
            float4 v;
            unpack2(acc2[j][c * 2], v.x, v.y);
            unpack2(acc2[j][c * 2 + 1], v.z, v.w);
            v.x *= SCALE; v.y *= SCALE; v.z *= SCALE; v.w *= SCALE;
            *reinterpret_cast<float4*>(&op[c * 4]) = v;
        }
    }
}

// ---------------------------------------------------------------------------
extern "C" void kernel_launch(void* const* d_in, const int* in_sizes, int n_in,
                              void* d_out, int out_size) {
    const float* x = (const float*)d_in[0];   // [512, 4096]
    const float* W = (const float*)d_in[1];   // [512, 1536]
    const float* b = (const float*)d_in[2];   // [1536]

    float* coarse = (float*)d_out;
    float* out    = (float*)d_out + HEADS * TOK;

    __half *ahi, *bhi;
    cudaGetSymbolAddress((void**)&ahi, g_a_hi);
    cudaGetSymbolAddress((void**)&bhi, g_b_hi);

    cudaFuncSetAttribute(qkv_gemm_mma, cudaFuncAttributeMaxDynamicSharedMemorySize, SM_TOT);
    cudaFuncSetAttribute(out_kernel, cudaFuncAttributeMaxDynamicSharedMemorySize, OSM_TOT);

    conv_transpose<<<dim3(TOK / 32, EMB / 32), 256>>>(x, ahi, TOK);
    conv_transpose<<<dim3(QKVN / 32, EMB / 32), 256>>>(W, bhi, QKVN);

    qkv_gemm_mma<<<dim3(QKVN / GBN, TOK / GBM), 256, SM_TOT>>>(b);

    ktv_kernel<<<dim3(HEADS, 32), 128>>>();
    ktv_reduce<<<128, 256>>>();
    out_kernel<<<dim3(HEADS, 32), 128, OSM_TOT>>>(coarse, out);
}

// round 10
// speedup vs baseline: 6.2206x; 6.2206x over previous
#include <cuda_runtime.h>
#include <cuda_fp16.h>
#include <cstdint>

#define TOK   4096
#define EMB   512
#define QKVN  1536
#define HEADS 8
#define DH    64
#define SCALE 0.125f

#define HSTRIDE (TOK * DH)           // 262144
#define PSTRIDE (HEADS * TOK * DH)   // 2097152

// ---------------- scratch (device globals) ----------------
__device__ float g_qkv[3 * HEADS * TOK * DH];        // [part][h][n][d]
__device__ float g_qsum[HEADS * DH];
__device__ float g_qsum_part[32 * HEADS * DH];       // [m_block][h*64+d]
__device__ float g_ktv[HEADS * DH * DH];
__device__ float g_ktv_part[32 * HEADS * DH * DH];

__device__ __half g_a_hi[TOK * EMB];                 // A = x^T  [4096, 512]
__device__ __half g_b_hi[QKVN * EMB];                // B = W^T  [1536, 512]

// ---------------- helpers ----------------
__device__ __forceinline__ uint32_t smem_u32(const void* p) {
    uint32_t a;
    asm("{ .reg .u64 t; cvta.to.shared.u64 t, %1; cvt.u32.u64 %0, t; }" : "=r"(a) : "l"(p));
    return a;
}
__device__ __forceinline__ uint32_t lds32(uint32_t a) {
    uint32_t v;
    asm volatile("ld.shared.b32 %0, [%1];" : "=r"(v) : "r"(a));
    return v;
}
__device__ __forceinline__ void cp_async16(uint32_t saddr, const void* gaddr) {
    asm volatile("cp.async.cg.shared.global [%0], [%1], 16;" :: "r"(saddr), "l"(gaddr));
}
__device__ __forceinline__ void cp_commit() { asm volatile("cp.async.commit_group;"); }
__device__ __forceinline__ void cp_wait1()  { asm volatile("cp.async.wait_group 1;"); }
__device__ __forceinline__ void cp_wait0()  { asm volatile("cp.async.wait_group 0;"); }

__device__ __forceinline__ void mma_f16(float& c0, float& c1, float& c2, float& c3,
                                        uint32_t a0, uint32_t a1, uint32_t a2, uint32_t a3,
                                        uint32_t b0, uint32_t b1) {
    asm volatile(
        "mma.sync.aligned.m16n8k16.row.col.f32.f16.f16.f32 "
        "{%0,%1,%2,%3}, {%4,%5,%6,%7}, {%8,%9}, {%0,%1,%2,%3};"
        : "+f"(c0), "+f"(c1), "+f"(c2), "+f"(c3)
        : "r"(a0), "r"(a1), "r"(a2), "r"(a3), "r"(b0), "r"(b1));
}

// packed fp32x2 (Blackwell FFMA2 path, exact fp32 semantics)
__device__ __forceinline__ unsigned long long dup2(float x) {
    unsigned long long r;
    asm("mov.b64 %0, {%1, %1};" : "=l"(r) : "f"(x));
    return r;
}
__device__ __forceinline__ unsigned long long fma2(unsigned long long a,
                                                   unsigned long long b,
                                                   unsigned long long c) {
    unsigned long long d;
    asm("fma.rn.f32x2 %0, %1, %2, %3;" : "=l"(d) : "l"(a), "l"(b), "l"(c));
    return d;
}
__device__ __forceinline__ void unpack2(unsigned long long v, float& x, float& y) {
    asm("mov.b64 {%0, %1}, %2;" : "=f"(x), "=f"(y) : "l"(v));
}
__device__ __forceinline__ void lds_v2u64(uint32_t addr, unsigned long long& a,
                                          unsigned long long& b) {
    asm volatile("ld.shared.v2.u64 {%0, %1}, [%2];" : "=l"(a), "=l"(b) : "r"(addr));
}

// ---------------------------------------------------------------------------
// Merged pre-pass: transpose x[512,4096]->ahi and W[512,1536]->bhi (one launch)
// ---------------------------------------------------------------------------
#define XBLKS (TOK / 32)      // 128
__global__ __launch_bounds__(256) void conv_transpose2(const float* __restrict__ x,
                                                       const float* __restrict__ W,
                                                       __half* __restrict__ ahi,
                                                       __half* __restrict__ bhi) {
    __shared__ float tile[32][33];
    int tx = threadIdx.x & 31, ty = threadIdx.x >> 5;
    int bx = blockIdx.x;
    const float* src;
    __half* dst;
    int Mcols, m0;
    if (bx < XBLKS) { src = x; dst = ahi; Mcols = TOK;  m0 = bx * 32; }
    else            { src = W; dst = bhi; Mcols = QKVN; m0 = (bx - XBLKS) * 32; }
    int k0 = blockIdx.y * 32;
#pragma unroll
    for (int j = 0; j < 4; j++)
        tile[ty + j * 8][tx] = src[(size_t)(k0 + ty + j * 8) * Mcols + m0 + tx];
    __syncthreads();
#pragma unroll
    for (int j = 0; j < 4; j++) {
        int m = m0 + ty + j * 8;
        dst[(size_t)m * EMB + k0 + tx] = __float2half_rn(tile[tx][ty + j * 8]);
    }
}

// ---------------------------------------------------------------------------
// mma.sync QKV GEMM (round-7, unchanged)
// ---------------------------------------------------------------------------
#define GBM 128
#define GBN 128
#define GBK 32
#define ROWB   80
#define TILE_B (128 * ROWB)
#define T_AHI  0
#define T_BHI  (1 * TILE_B)
#define STG_B  (2 * TILE_B)
#define SM_BIAS (2 * STG_B)
#define SM_QS   (SM_BIAS + 512)
#define SM_TOT  (SM_QS + 1024)

__global__ void __launch_bounds__(256, 2) qkv_gemm_mma(const float* __restrict__ bias) {
    extern __shared__ char smem[];
    const uint32_t sb = smem_u32(smem);
    const int tid  = threadIdx.x;
    const int wid  = tid >> 5;
    const int lane = tid & 31;
    const int g    = lane >> 2;
    const int tg   = lane & 3;
    const int wm   = wid >> 2;
    const int wn   = wid & 3;
    const int o0   = blockIdx.x * GBN;
    const int m0   = blockIdx.y * GBM;

    if (tid < 128) *reinterpret_cast<float*>(smem + SM_BIAS + tid * 4) = bias[o0 + tid];

    const __half* srcs[2] = {
        &g_a_hi[(size_t)m0 * EMB], &g_b_hi[(size_t)o0 * EMB]};

    auto issue = [&](int chunk) {
        const int kt = chunk * GBK;
        const uint32_t stage = sb + (chunk & 1) * STG_B;
#pragma unroll
        for (int t = 0; t < 2; t++) {
            const __half* gp = srcs[t] + kt;
            const uint32_t tb = stage + t * TILE_B;
#pragma unroll
            for (int i = 0; i < 2; i++) {
                int lin = tid + i * 256;
                int row = lin >> 2;
                int seg = lin & 3;
                cp_async16(tb + row * ROWB + seg * 16, gp + (size_t)row * EMB + seg * 8);
            }
        }
        cp_commit();
    };

    float acc[4][4][4];
#pragma unroll
    for (int i = 0; i < 4; i++)
#pragma unroll
        for (int j = 0; j < 4; j++)
#pragma unroll
            for (int c = 0; c < 4; c++) acc[i][j][c] = 0.f;

    issue(0);

    const uint32_t aRow0 = wm * 64 + g;
    const uint32_t bRow0 = wn * 32 + g;

    for (int chunk = 0; chunk < EMB / GBK; ++chunk) {
        if (chunk + 1 < EMB / GBK) { issue(chunk + 1); cp_wait1(); }
        else                       { cp_wait0(); }
        __syncthreads();

        const uint32_t stage = sb + (chunk & 1) * STG_B;

#pragma unroll
        for (int kk = 0; kk < 2; kk++) {
            const uint32_t klo = kk * 32 + tg * 4;

            uint32_t afr[4][4], bfr[4][2];
#pragma unroll
            for (int nt = 0; nt < 4; nt++) {
                uint32_t base = stage + (bRow0 + nt * 8) * ROWB + klo + T_BHI;
                bfr[nt][0] = lds32(base);
                bfr[nt][1] = lds32(base + 16);
            }
#pragma unroll
            for (int mt = 0; mt < 4; mt++) {
                uint32_t base = stage + (aRow0 + mt * 16) * ROWB + klo + T_AHI;
                afr[mt][0] = lds32(base);
                afr[mt][1] = lds32(base + 8 * ROWB);
                afr[mt][2] = lds32(base + 16);
                afr[mt][3] = lds32(base + 8 * ROWB + 16);
            }
#pragma unroll
            for (int mt = 0; mt < 4; mt++)
#pragma unroll
                for (int nt = 0; nt < 4; nt++)
                    mma_f16(acc[mt][nt][0], acc[mt][nt][1], acc[mt][nt][2], acc[mt][nt][3],
                            afr[mt][0], afr[mt][1], afr[mt][2], afr[mt][3],
                            bfr[nt][0], bfr[nt][1]);
        }
        __syncthreads();
    }

    const float* sbias = reinterpret_cast<const float*>(smem + SM_BIAS);
#pragma unroll
    for (int mt = 0; mt < 4; mt++) {
        const int m = m0 + wm * 64 + mt * 16 + g;
#pragma unroll
        for (int nt = 0; nt < 4; nt++) {
            const int off = wn * 32 + nt * 8 + 2 * tg;
            const int o = o0 + off;
            const int part = o >> 9;
            const int h = (o >> 6) & 7;
            const int d = o & 63;
            const float bv0 = sbias[off], bv1 = sbias[off + 1];
            float* base = &g_qkv[(size_t)part * PSTRIDE + (size_t)h * HSTRIDE];
            float2 r0 = {acc[mt][nt][0] + bv0, acc[mt][nt][1] + bv1};
            float2 r1 = {acc[mt][nt][2] + bv0, acc[mt][nt][3] + bv1};
            *reinterpret_cast<float2*>(&base[(size_t)m * DH + d]) = r0;
            *reinterpret_cast<float2*>(&base[(size_t)(m + 8) * DH + d]) = r1;
        }
    }

    // fused qsum partial
    if (o0 < 512) {
        float* qs = reinterpret_cast<float*>(smem + SM_QS);
        float cs[8];
#pragma unroll
        for (int nt = 0; nt < 4; nt++)
#pragma unroll
            for (int j = 0; j < 2; j++) {
                const int off = wn * 32 + nt * 8 + 2 * tg + j;
                float s = 8.f * sbias[off];
#pragma unroll
                for (int mt = 0; mt < 4; mt++)
                    s += acc[mt][nt][j] + acc[mt][nt][j + 2];
                cs[nt * 2 + j] = s;
            }
#pragma unroll
        for (int i = 0; i < 8; i++) {
#pragma unroll
            for (int off = 4; off < 32; off <<= 1)
                cs[i] += __shfl_xor_sync(0xffffffffu, cs[i], off);
        }
        if (g == 0) {
#pragma unroll
            for (int nt = 0; nt < 4; nt++)
#pragma unroll
                for (int j = 0; j < 2; j++)
                    qs[wm * 128 + wn * 32 + nt * 8 + 2 * tg + j] = cs[nt * 2 + j];
        }
        __syncthreads();
        if (tid < 128)
            g_qsum_part[blockIdx.y * 512 + o0 + tid] = qs[tid] + qs[128 + tid];
    }
}

// ---------------------------------------------------------------------------
// partial KtV over 32 N-splits — r7 math, + cp.async 2-stage prefetch
// ---------------------------------------------------------------------------
__global__ __launch_bounds__(128) void ktv_kernel() {
    int h = blockIdx.x;
    int split = blockIdx.y;
    const float* Kp = &g_qkv[(size_t)1 * PSTRIDE + (size_t)h * HSTRIDE + (size_t)split * 128 * DH];
    const float* Vp = &g_qkv[(size_t)2 * PSTRIDE + (size_t)h * HSTRIDE + (size_t)split * 128 * DH];

    __shared__ float sK[2][32][64];
    __shared__ float sV[2][32][64];
    const uint32_t sKb = smem_u32(sK);
    const uint32_t sVb = smem_u32(sV);

    int tid = threadIdx.x;
    int d1b = (tid >> 4) * 8;
    int d2b = (tid & 15) * 4;

    // cp.async issue for one 32-row stage: 512 float4s per array / 128 thr
    auto issue = [&](int s) {
        const int nb = s * 32;
        const uint32_t st = (s & 1) * (32 * 64 * 4);
#pragma unroll
        for (int i = 0; i < 4; i++) {
            int lin = tid + i * 128;       // 0..511
            int r = lin >> 4;
            int c = (lin & 15) << 2;
            cp_async16(sKb + st + (r * 64 + c) * 4, &Kp[(size_t)(nb + r) * DH + c]);
            cp_async16(sVb + st + (r * 64 + c) * 4, &Vp[(size_t)(nb + r) * DH + c]);
        }
        cp_commit();
    };

    unsigned long long acc2[8][2];
#pragma unroll
    for (int i = 0; i < 8; i++) { acc2[i][0] = 0ull; acc2[i][1] = 0ull; }

    issue(0);
    for (int s = 0; s < 4; s++) {
        if (s + 1 < 4) { issue(s + 1); cp_wait1(); }
        else           { cp_wait0(); }
        __syncthreads();

        const float(*cK)[64] = sK[s & 1];
        const uint32_t vst = sVb + (s & 1) * (32 * 64 * 4);
#pragma unroll
        for (int nn = 0; nn < 32; nn++) {
            float4 k0 = *reinterpret_cast<const float4*>(&cK[nn][d1b]);
            float4 k1 = *reinterpret_cast<const float4*>(&cK[nn][d1b + 4]);
            unsigned long long v01, v23;
            lds_v2u64(vst + (nn * 64 + d2b) * 4, v01, v23);
            unsigned long long kd;
            kd = dup2(k0.x); acc2[0][0] = fma2(kd, v01, acc2[0][0]); acc2[0][1] = fma2(kd, v23, acc2[0][1]);
            kd = dup2(k0.y); acc2[1][0] = fma2(kd, v01, acc2[1][0]); acc2[1][1] = fma2(kd, v23, acc2[1][1]);
            kd = dup2(k0.z); acc2[2][0] = fma2(kd, v01, acc2[2][0]); acc2[2][1] = fma2(kd, v23, acc2[2][1]);
            kd = dup2(k0.w); acc2[3][0] = fma2(kd, v01, acc2[3][0]); acc2[3][1] = fma2(kd, v23, acc2[3][1]);
            kd = dup2(k1.x); acc2[4][0] = fma2(kd, v01, acc2[4][0]); acc2[4][1] = fma2(kd, v23, acc2[4][1]);
            kd = dup2(k1.y); acc2[5][0] = fma2(kd, v01, acc2[5][0]); acc2[5][1] = fma2(kd, v23, acc2[5][1]);
            kd = dup2(k1.z); acc2[6][0] = fma2(kd, v01, acc2[6][0]); acc2[6][1] = fma2(kd, v23, acc2[6][1]);
            kd = dup2(k1.w); acc2[7][0] = fma2(kd, v01, acc2[7][0]); acc2[7][1] = fma2(kd, v23, acc2[7][1]);
        }
        __syncthreads();
    }

    float* dst = &g_ktv_part[(size_t)split * (HEADS * DH * DH) + (size_t)h * DH * DH];
#pragma unroll
    for (int i = 0; i < 8; i++) {
        float4 v;
        unpack2(acc2[i][0], v.x, v.y);
        unpack2(acc2[i][1], v.z, v.w);
        *reinterpret_cast<float4*>(&dst[(d1b + i) * DH + d2b]) = v;
    }
}

// ktv reduce + fused qsum reduce (round-7, unchanged)
__global__ void ktv_reduce() {
    int i = blockIdx.x * 256 + threadIdx.x;
    float s = 0.f;
#pragma unroll
    for (int sp = 0; sp < 32; sp++) s += g_ktv_part[(size_t)sp * (HEADS * DH * DH) + i];
    g_ktv[i] = s;
    if (i < HEADS * DH) {
        float q = 0.f;
#pragma unroll
        for (int sp = 0; sp < 32; sp++) q += g_qsum_part[sp * (HEADS * DH) + i];
        g_qsum[i] = q;
    }
}

// ---------------------------------------------------------------------------
// out (round-7, unchanged): 1 row/thread, full-M broadcast sweep, f32x2
// ---------------------------------------------------------------------------
#define OQ_PAD 65
#define OSM_M   0                          // 64*64 floats = 16384 B
#define OSM_Q   16384                      // 128*65 floats = 33280 B
#define OSM_QS  (OSM_Q + 128 * OQ_PAD * 4) // 49664
#define OSM_TOT (OSM_QS + 256)             // 49920

__global__ void __launch_bounds__(128, 1) out_kernel(float* __restrict__ coarse,
                                                     float* __restrict__ out) {
    extern __shared__ char osm[];
    float* sM  = reinterpret_cast<float*>(osm + OSM_M);
    float* sQ  = reinterpret_cast<float*>(osm + OSM_Q);
    float* sQs = reinterpret_cast<float*>(osm + OSM_QS);
    const uint32_t sMb = smem_u32(sM);
    const uint32_t sQb = smem_u32(sQ);

    int h = blockIdx.x;
    int nt = blockIdx.y;
    int tid = threadIdx.x;
    int n = nt * 128 + tid;

#pragma unroll
    for (int i = 0; i < 8; i++) {
        int lin = tid + i * 128;
        *reinterpret_cast<float4*>(&sM[lin * 4]) =
            *reinterpret_cast<const float4*>(&g_ktv[(size_t)h * DH * DH + lin * 4]);
    }
    if (tid < 64) sQs[tid] = g_qsum[h * 64 + tid];

    const float* Qg = &g_qkv[(size_t)h * HSTRIDE + (size_t)nt * 128 * DH];
#pragma unroll
    for (int i = 0; i < 16; i++) {
        int lin = tid + i * 128;
        int r = lin >> 4;
        int c = (lin & 15) * 4;
        float4 v = *reinterpret_cast<const float4*>(&Qg[(size_t)r * DH + c]);
        float* dq = &sQ[r * OQ_PAD + c];
        dq[0] = v.x; dq[1] = v.y; dq[2] = v.z; dq[3] = v.w;
    }
    __syncthreads();

    const float* Kr = &g_qkv[(size_t)1 * PSTRIDE + (size_t)h * HSTRIDE + (size_t)n * DH];
    float cacc = 0.f;
#pragma unroll
    for (int d4 = 0; d4 < 64; d4 += 4) {
        float4 k4 = *reinterpret_cast<const float4*>(&Kr[d4]);
        cacc += k4.x * sQs[d4] + k4.y * sQs[d4 + 1] + k4.z * sQs[d4 + 2] + k4.w * sQs[d4 + 3];
    }
    coarse[h * TOK + n] = cacc * SCALE;

    unsigned long long acc2[32];
#pragma unroll
    for (int i = 0; i < 32; i++) acc2[i] = 0ull;

    const uint32_t qrow = sQb + tid * (OQ_PAD * 4);
#pragma unroll 8
    for (int d1 = 0; d1 < 64; d1++) {
        unsigned long long qd = dup2(__uint_as_float(lds32(qrow + d1 * 4)));
        const uint32_t mrow = sMb + d1 * 256;
#pragma unroll
        for (int c = 0; c < 16; c++) {
            unsigned long long m0, m1;
            lds_v2u64(mrow + c * 16, m0, m1);
            acc2[c * 2]     = fma2(qd, m0, acc2[c * 2]);
            acc2[c * 2 + 1] = fma2(qd, m1, acc2[c * 2 + 1]);
        }
    }

    float* op = &out[((size_t)h * TOK + n) * DH];
#pragma unroll
    for (int c = 0; c < 16; c++) {
        float4 v;
        unpack2(acc2[c * 2], v.x, v.y);
        unpack2(acc2[c * 2 + 1], v.z, v.w);
        v.x *= SCALE; v.y *= SCALE; v.z *= SCALE; v.w *= SCALE;
        *reinterpret_cast<float4*>(&op[c * 4]) = v;
    }
}

// ---------------------------------------------------------------------------
extern "C" void kernel_launch(void* const* d_in, const int* in_sizes, int n_in,
                              void* d_out, int out_size) {
    const float* x = (const float*)d_in[0];   // [512, 4096]
    const float* W = (const float*)d_in[1];   // [512, 1536]
    const float* b = (const float*)d_in[2];   // [1536]

    float* coarse = (float*)d_out;
    float* out    = (float*)d_out + HEADS * TOK;

    __half *ahi, *bhi;
    cudaGetSymbolAddress((void**)&ahi, g_a_hi);
    cudaGetSymbolAddress((void**)&bhi, g_b_hi);

    cudaFuncSetAttribute(qkv_gemm_mma, cudaFuncAttributeMaxDynamicSharedMemorySize, SM_TOT);
    cudaFuncSetAttribute(out_kernel, cudaFuncAttributeMaxDynamicSharedMemorySize, OSM_TOT);

    conv_transpose2<<<dim3(XBLKS + QKVN / 32, EMB / 32), 256>>>(x, W, ahi, bhi);

    qkv_gemm_mma<<<dim3(QKVN / GBN, TOK / GBM), 256, SM_TOT>>>(b);

    ktv_kernel<<<dim3(HEADS, 32), 128>>>();
    ktv_reduce<<<128, 256>>>();
    out_kernel<<<dim3(HEADS, 32), 128, OSM_TOT>>>(coarse, out);
}

// round 11
// speedup vs baseline: 6.2598x; 1.0063x over previous
#include <cuda_runtime.h>
#include <cuda_fp16.h>
#include <cstdint>

#define TOK   4096
#define EMB   512
#define QKVN  1536
#define HEADS 8
#define DH    64
#define SCALE 0.125f

#define HSTRIDE (TOK * DH)           // 262144
#define PSTRIDE (HEADS * TOK * DH)   // 2097152

// ---------------- scratch (device globals) ----------------
__device__ float g_qkv[3 * HEADS * TOK * DH];        // [part][h][n][d]
__device__ float g_qsum[HEADS * DH];
__device__ float g_qsum_part[32 * HEADS * DH];       // [m_block][h*64+d]
__device__ float g_ktv[HEADS * DH * DH];
__device__ float g_ktv_part[32 * HEADS * DH * DH];

__device__ __half g_a_hi[TOK * EMB];                 // A = x^T  [4096, 512]
__device__ __half g_b_hi[QKVN * EMB];                // B = W^T  [1536, 512]

// ---------------- helpers ----------------
__device__ __forceinline__ uint32_t smem_u32(const void* p) {
    uint32_t a;
    asm("{ .reg .u64 t; cvta.to.shared.u64 t, %1; cvt.u32.u64 %0, t; }" : "=r"(a) : "l"(p));
    return a;
}
__device__ __forceinline__ uint32_t lds32(uint32_t a) {
    uint32_t v;
    asm volatile("ld.shared.b32 %0, [%1];" : "=r"(v) : "r"(a));
    return v;
}
__device__ __forceinline__ void cp_async16(uint32_t saddr, const void* gaddr) {
    asm volatile("cp.async.cg.shared.global [%0], [%1], 16;" :: "r"(saddr), "l"(gaddr));
}
__device__ __forceinline__ void cp_commit() { asm volatile("cp.async.commit_group;"); }
__device__ __forceinline__ void cp_wait1()  { asm volatile("cp.async.wait_group 1;"); }
__device__ __forceinline__ void cp_wait0()  { asm volatile("cp.async.wait_group 0;"); }

__device__ __forceinline__ void mma_f16(float& c0, float& c1, float& c2, float& c3,
                                        uint32_t a0, uint32_t a1, uint32_t a2, uint32_t a3,
                                        uint32_t b0, uint32_t b1) {
    asm volatile(
        "mma.sync.aligned.m16n8k16.row.col.f32.f16.f16.f32 "
        "{%0,%1,%2,%3}, {%4,%5,%6,%7}, {%8,%9}, {%0,%1,%2,%3};"
        : "+f"(c0), "+f"(c1), "+f"(c2), "+f"(c3)
        : "r"(a0), "r"(a1), "r"(a2), "r"(a3), "r"(b0), "r"(b1));
}

// packed fp32x2 (Blackwell FFMA2 path, exact fp32 semantics)
__device__ __forceinline__ unsigned long long dup2(float x) {
    unsigned long long r;
    asm("mov.b64 %0, {%1, %1};" : "=l"(r) : "f"(x));
    return r;
}
__device__ __forceinline__ unsigned long long fma2(unsigned long long a,
                                                   unsigned long long b,
                                                   unsigned long long c) {
    unsigned long long d;
    asm("fma.rn.f32x2 %0, %1, %2, %3;" : "=l"(d) : "l"(a), "l"(b), "l"(c));
    return d;
}
__device__ __forceinline__ void unpack2(unsigned long long v, float& x, float& y) {
    asm("mov.b64 {%0, %1}, %2;" : "=f"(x), "=f"(y) : "l"(v));
}
__device__ __forceinline__ void lds_v2u64(uint32_t addr, unsigned long long& a,
                                          unsigned long long& b) {
    asm volatile("ld.shared.v2.u64 {%0, %1}, [%2];" : "=l"(a), "=l"(b) : "r"(addr));
}

// ---------------------------------------------------------------------------
// Merged pre-pass: transpose x->ahi and W->bhi, half2 stores
// ---------------------------------------------------------------------------
#define XBLKS (TOK / 32)      // 128
__global__ __launch_bounds__(256) void conv_transpose2(const float* __restrict__ x,
                                                       const float* __restrict__ W,
                                                       __half* __restrict__ ahi,
                                                       __half* __restrict__ bhi) {
    __shared__ float tile[32][33];
    int tid = threadIdx.x;
    int tx = tid & 31, ty = tid >> 5;
    int bx = blockIdx.x;
    const float* src;
    __half* dst;
    int Mcols, m0;
    if (bx < XBLKS) { src = x; dst = ahi; Mcols = TOK;  m0 = bx * 32; }
    else            { src = W; dst = bhi; Mcols = QKVN; m0 = (bx - XBLKS) * 32; }
    int k0 = blockIdx.y * 32;
#pragma unroll
    for (int j = 0; j < 4; j++)
        tile[ty + j * 8][tx] = src[(size_t)(k0 + ty + j * 8) * Mcols + m0 + tx];
    __syncthreads();
    // write: 32 rows x 16 half2; thread (r2, c2) with r2 = tid>>4 (0..15), c2 = tid&15
    int r2 = tid >> 4;
    int c2 = tid & 15;
#pragma unroll
    for (int j = 0; j < 2; j++) {
        int row = r2 + j * 16;                 // m - m0
        int m = m0 + row;
        __half2 v = __floats2half2_rn(tile[c2 * 2][row], tile[c2 * 2 + 1][row]);
        *reinterpret_cast<__half2*>(&dst[(size_t)m * EMB + k0 + c2 * 2]) = v;
    }
}

// ---------------------------------------------------------------------------
// mma.sync QKV GEMM (unchanged)
// ---------------------------------------------------------------------------
#define GBM 128
#define GBN 128
#define GBK 32
#define ROWB   80
#define TILE_B (128 * ROWB)
#define T_AHI  0
#define T_BHI  (1 * TILE_B)
#define STG_B  (2 * TILE_B)
#define SM_BIAS (2 * STG_B)
#define SM_QS   (SM_BIAS + 512)
#define SM_TOT  (SM_QS + 1024)

__global__ void __launch_bounds__(256, 2) qkv_gemm_mma(const float* __restrict__ bias) {
    extern __shared__ char smem[];
    const uint32_t sb = smem_u32(smem);
    const int tid  = threadIdx.x;
    const int wid  = tid >> 5;
    const int lane = tid & 31;
    const int g    = lane >> 2;
    const int tg   = lane & 3;
    const int wm   = wid >> 2;
    const int wn   = wid & 3;
    const int o0   = blockIdx.x * GBN;
    const int m0   = blockIdx.y * GBM;

    if (tid < 128) *reinterpret_cast<float*>(smem + SM_BIAS + tid * 4) = bias[o0 + tid];

    const __half* srcs[2] = {
        &g_a_hi[(size_t)m0 * EMB], &g_b_hi[(size_t)o0 * EMB]};

    auto issue = [&](int chunk) {
        const int kt = chunk * GBK;
        const uint32_t stage = sb + (chunk & 1) * STG_B;
#pragma unroll
        for (int t = 0; t < 2; t++) {
            const __half* gp = srcs[t] + kt;
            const uint32_t tb = stage + t * TILE_B;
#pragma unroll
            for (int i = 0; i < 2; i++) {
                int lin = tid + i * 256;
                int row = lin >> 2;
                int seg = lin & 3;
                cp_async16(tb + row * ROWB + seg * 16, gp + (size_t)row * EMB + seg * 8);
            }
        }
        cp_commit();
    };

    float acc[4][4][4];
#pragma unroll
    for (int i = 0; i < 4; i++)
#pragma unroll
        for (int j = 0; j < 4; j++)
#pragma unroll
            for (int c = 0; c < 4; c++) acc[i][j][c] = 0.f;

    issue(0);

    const uint32_t aRow0 = wm * 64 + g;
    const uint32_t bRow0 = wn * 32 + g;

    for (int chunk = 0; chunk < EMB / GBK; ++chunk) {
        if (chunk + 1 < EMB / GBK) { issue(chunk + 1); cp_wait1(); }
        else                       { cp_wait0(); }
        __syncthreads();

        const uint32_t stage = sb + (chunk & 1) * STG_B;

#pragma unroll
        for (int kk = 0; kk < 2; kk++) {
            const uint32_t klo = kk * 32 + tg * 4;

            uint32_t afr[4][4], bfr[4][2];
#pragma unroll
            for (int nt = 0; nt < 4; nt++) {
                uint32_t base = stage + (bRow0 + nt * 8) * ROWB + klo + T_BHI;
                bfr[nt][0] = lds32(base);
                bfr[nt][1] = lds32(base + 16);
            }
#pragma unroll
            for (int mt = 0; mt < 4; mt++) {
                uint32_t base = stage + (aRow0 + mt * 16) * ROWB + klo + T_AHI;
                afr[mt][0] = lds32(base);
                afr[mt][1] = lds32(base + 8 * ROWB);
                afr[mt][2] = lds32(base + 16);
                afr[mt][3] = lds32(base + 8 * ROWB + 16);
            }
#pragma unroll
            for (int mt = 0; mt < 4; mt++)
#pragma unroll
                for (int nt = 0; nt < 4; nt++)
                    mma_f16(acc[mt][nt][0], acc[mt][nt][1], acc[mt][nt][2], acc[mt][nt][3],
                            afr[mt][0], afr[mt][1], afr[mt][2], afr[mt][3],
                            bfr[nt][0], bfr[nt][1]);
        }
        __syncthreads();
    }

    const float* sbias = reinterpret_cast<const float*>(smem + SM_BIAS);
#pragma unroll
    for (int mt = 0; mt < 4; mt++) {
        const int m = m0 + wm * 64 + mt * 16 + g;
#pragma unroll
        for (int nt = 0; nt < 4; nt++) {
            const int off = wn * 32 + nt * 8 + 2 * tg;
            const int o = o0 + off;
            const int part = o >> 9;
            const int h = (o >> 6) & 7;
            const int d = o & 63;
            const float bv0 = sbias[off], bv1 = sbias[off + 1];
            float* base = &g_qkv[(size_t)part * PSTRIDE + (size_t)h * HSTRIDE];
            float2 r0 = {acc[mt][nt][0] + bv0, acc[mt][nt][1] + bv1};
            float2 r1 = {acc[mt][nt][2] + bv0, acc[mt][nt][3] + bv1};
            *reinterpret_cast<float2*>(&base[(size_t)m * DH + d]) = r0;
            *reinterpret_cast<float2*>(&base[(size_t)(m + 8) * DH + d]) = r1;
        }
    }

    // fused qsum partial
    if (o0 < 512) {
        float* qs = reinterpret_cast<float*>(smem + SM_QS);
        float cs[8];
#pragma unroll
        for (int nt = 0; nt < 4; nt++)
#pragma unroll
            for (int j = 0; j < 2; j++) {
                const int off = wn * 32 + nt * 8 + 2 * tg + j;
                float s = 8.f * sbias[off];
#pragma unroll
                for (int mt = 0; mt < 4; mt++)
                    s += acc[mt][nt][j] + acc[mt][nt][j + 2];
                cs[nt * 2 + j] = s;
            }
#pragma unroll
        for (int i = 0; i < 8; i++) {
#pragma unroll
            for (int off = 4; off < 32; off <<= 1)
                cs[i] += __shfl_xor_sync(0xffffffffu, cs[i], off);
        }
        if (g == 0) {
#pragma unroll
            for (int nt = 0; nt < 4; nt++)
#pragma unroll
                for (int j = 0; j < 2; j++)
                    qs[wm * 128 + wn * 32 + nt * 8 + 2 * tg + j] = cs[nt * 2 + j];
        }
        __syncthreads();
        if (tid < 128)
            g_qsum_part[blockIdx.y * 512 + o0 + tid] = qs[tid] + qs[128 + tid];
    }
}

// ---------------------------------------------------------------------------
// partial KtV over 32 N-splits — cp.async 2-stage prefetch (unchanged)
// ---------------------------------------------------------------------------
__global__ __launch_bounds__(128) void ktv_kernel() {
    int h = blockIdx.x;
    int split = blockIdx.y;
    const float* Kp = &g_qkv[(size_t)1 * PSTRIDE + (size_t)h * HSTRIDE + (size_t)split * 128 * DH];
    const float* Vp = &g_qkv[(size_t)2 * PSTRIDE + (size_t)h * HSTRIDE + (size_t)split * 128 * DH];

    __shared__ float sK[2][32][64];
    __shared__ float sV[2][32][64];
    const uint32_t sKb = smem_u32(sK);
    const uint32_t sVb = smem_u32(sV);

    int tid = threadIdx.x;
    int d1b = (tid >> 4) * 8;
    int d2b = (tid & 15) * 4;

    auto issue = [&](int s) {
        const int nb = s * 32;
        const uint32_t st = (s & 1) * (32 * 64 * 4);
#pragma unroll
        for (int i = 0; i < 4; i++) {
            int lin = tid + i * 128;
            int r = lin >> 4;
            int c = (lin & 15) << 2;
            cp_async16(sKb + st + (r * 64 + c) * 4, &Kp[(size_t)(nb + r) * DH + c]);
            cp_async16(sVb + st + (r * 64 + c) * 4, &Vp[(size_t)(nb + r) * DH + c]);
        }
        cp_commit();
    };

    unsigned long long acc2[8][2];
#pragma unroll
    for (int i = 0; i < 8; i++) { acc2[i][0] = 0ull; acc2[i][1] = 0ull; }

    issue(0);
    for (int s = 0; s < 4; s++) {
        if (s + 1 < 4) { issue(s + 1); cp_wait1(); }
        else           { cp_wait0(); }
        __syncthreads();

        const float(*cK)[64] = sK[s & 1];
        const uint32_t vst = sVb + (s & 1) * (32 * 64 * 4);
#pragma unroll
        for (int nn = 0; nn < 32; nn++) {
            float4 k0 = *reinterpret_cast<const float4*>(&cK[nn][d1b]);
            float4 k1 = *reinterpret_cast<const float4*>(&cK[nn][d1b + 4]);
            unsigned long long v01, v23;
            lds_v2u64(vst + (nn * 64 + d2b) * 4, v01, v23);
            unsigned long long kd;
            kd = dup2(k0.x); acc2[0][0] = fma2(kd, v01, acc2[0][0]); acc2[0][1] = fma2(kd, v23, acc2[0][1]);
            kd = dup2(k0.y); acc2[1][0] = fma2(kd, v01, acc2[1][0]); acc2[1][1] = fma2(kd, v23, acc2[1][1]);
            kd = dup2(k0.z); acc2[2][0] = fma2(kd, v01, acc2[2][0]); acc2[2][1] = fma2(kd, v23, acc2[2][1]);
            kd = dup2(k0.w); acc2[3][0] = fma2(kd, v01, acc2[3][0]); acc2[3][1] = fma2(kd, v23, acc2[3][1]);
            kd = dup2(k1.x); acc2[4][0] = fma2(kd, v01, acc2[4][0]); acc2[4][1] = fma2(kd, v23, acc2[4][1]);
            kd = dup2(k1.y); acc2[5][0] = fma2(kd, v01, acc2[5][0]); acc2[5][1] = fma2(kd, v23, acc2[5][1]);
            kd = dup2(k1.z); acc2[6][0] = fma2(kd, v01, acc2[6][0]); acc2[6][1] = fma2(kd, v23, acc2[6][1]);
            kd = dup2(k1.w); acc2[7][0] = fma2(kd, v01, acc2[7][0]); acc2[7][1] = fma2(kd, v23, acc2[7][1]);
        }
        __syncthreads();
    }

    float* dst = &g_ktv_part[(size_t)split * (HEADS * DH * DH) + (size_t)h * DH * DH];
#pragma unroll
    for (int i = 0; i < 8; i++) {
        float4 v;
        unpack2(acc2[i][0], v.x, v.y);
        unpack2(acc2[i][1], v.z, v.w);
        *reinterpret_cast<float4*>(&dst[(d1b + i) * DH + d2b]) = v;
    }
}

// ---------------------------------------------------------------------------
// ktv reduce: 4 threads per output (8 loads each + 2 shfl steps), deterministic.
// qsum reduce folded in (first 2048 global threads).
// ---------------------------------------------------------------------------
__global__ __launch_bounds__(256) void ktv_reduce() {
    int gt = blockIdx.x * 256 + threadIdx.x;   // 0 .. 131071
    int o  = gt >> 2;                          // output index 0..32767
    int p  = gt & 3;                           // split quarter
    float s = 0.f;
#pragma unroll
    for (int j = 0; j < 8; j++)
        s += g_ktv_part[(size_t)(p * 8 + j) * (HEADS * DH * DH) + o];
    s += __shfl_xor_sync(0xffffffffu, s, 1);
    s += __shfl_xor_sync(0xffffffffu, s, 2);
    if (p == 0) g_ktv[o] = s;

    if (gt < 2048) {                           // qsum: 512 outputs x 4 threads
        int o2 = gt >> 2;
        float q = 0.f;
#pragma unroll
        for (int j = 0; j < 8; j++)
            q += g_qsum_part[(p * 8 + j) * (HEADS * DH) + o2];
        q += __shfl_xor_sync(0xffffffffu, q, 1);
        q += __shfl_xor_sync(0xffffffffu, q, 2);
        if (p == 0) g_qsum[o2] = q;
    }
}

// ---------------------------------------------------------------------------
// out (unchanged): 1 row/thread, full-M broadcast sweep, f32x2
// ---------------------------------------------------------------------------
#define OQ_PAD 65
#define OSM_M   0
#define OSM_Q   16384
#define OSM_QS  (OSM_Q + 128 * OQ_PAD * 4)
#define OSM_TOT (OSM_QS + 256)

__global__ void __launch_bounds__(128, 1) out_kernel(float* __restrict__ coarse,
                                                     float* __restrict__ out) {
    extern __shared__ char osm[];
    float* sM  = reinterpret_cast<float*>(osm + OSM_M);
    float* sQ  = reinterpret_cast<float*>(osm + OSM_Q);
    float* sQs = reinterpret_cast<float*>(osm + OSM_QS);
    const uint32_t sMb = smem_u32(sM);
    const uint32_t sQb = smem_u32(sQ);

    int h = blockIdx.x;
    int nt = blockIdx.y;
    int tid = threadIdx.x;
    int n = nt * 128 + tid;

#pragma unroll
    for (int i = 0; i < 8; i++) {
        int lin = tid + i * 128;
        *reinterpret_cast<float4*>(&sM[lin * 4]) =
            *reinterpret_cast<const float4*>(&g_ktv[(size_t)h * DH * DH + lin * 4]);
    }
    if (tid < 64) sQs[tid] = g_qsum[h * 64 + tid];

    const float* Qg = &g_qkv[(size_t)h * HSTRIDE + (size_t)nt * 128 * DH];
#pragma unroll
    for (int i = 0; i < 16; i++) {
        int lin = tid + i * 128;
        int r = lin >> 4;
        int c = (lin & 15) * 4;
        float4 v = *reinterpret_cast<const float4*>(&Qg[(size_t)r * DH + c]);
        float* dq = &sQ[r * OQ_PAD + c];
        dq[0] = v.x; dq[1] = v.y; dq[2] = v.z; dq[3] = v.w;
    }
    __syncthreads();

    const float* Kr = &g_qkv[(size_t)1 * PSTRIDE + (size_t)h * HSTRIDE + (size_t)n * DH];
    float cacc = 0.f;
#pragma unroll
    for (int d4 = 0; d4 < 64; d4 += 4) {
        float4 k4 = *reinterpret_cast<const float4*>(&Kr[d4]);
        cacc += k4.x * sQs[d4] + k4.y * sQs[d4 + 1] + k4.z * sQs[d4 + 2] + k4.w * sQs[d4 + 3];
    }
    coarse[h * TOK + n] = cacc * SCALE;

    unsigned long long acc2[32];
#pragma unroll
    for (int i = 0; i < 32; i++) acc2[i] = 0ull;

    const uint32_t qrow = sQb + tid * (OQ_PAD * 4);
#pragma unroll 8
    for (int d1 = 0; d1 < 64; d1++) {
        unsigned long long qd = dup2(__uint_as_float(lds32(qrow + d1 * 4)));
        const uint32_t mrow = sMb + d1 * 256;
#pragma unroll
        for (int c = 0; c < 16; c++) {
            unsigned long long m0, m1;
            lds_v2u64(mrow + c * 16, m0, m1);
            acc2[c * 2]     = fma2(qd, m0, acc2[c * 2]);
            acc2[c * 2 + 1] = fma2(qd, m1, acc2[c * 2 + 1]);
        }
    }

    float* op = &out[((size_t)h * TOK + n) * DH];
#pragma unroll
    for (int c = 0; c < 16; c++) {
        float4 v;
        unpack2(acc2[c * 2], v.x, v.y);
        unpack2(acc2[c * 2 + 1], v.z, v.w);
        v.x *= SCALE; v.y *= SCALE; v.z *= SCALE; v.w *= SCALE;
        *reinterpret_cast<float4*>(&op[c * 4]) = v;
    }
}

// ---------------------------------------------------------------------------
extern "C" void kernel_launch(void* const* d_in, const int* in_sizes, int n_in,
                              void* d_out, int out_size) {
    const float* x = (const float*)d_in[0];   // [512, 4096]
    const float* W = (const float*)d_in[1];   // [512, 1536]
    const float* b = (const float*)d_in[2];   // [1536]

    float* coarse = (float*)d_out;
    float* out    = (float*)d_out + HEADS * TOK;

    __half *ahi, *bhi;
    cudaGetSymbolAddress((void**)&ahi, g_a_hi);
    cudaGetSymbolAddress((void**)&bhi, g_b_hi);

    cudaFuncSetAttribute(qkv_gemm_mma, cudaFuncAttributeMaxDynamicSharedMemorySize, SM_TOT);
    cudaFuncSetAttribute(out_kernel, cudaFuncAttributeMaxDynamicSharedMemorySize, OSM_TOT);

    conv_transpose2<<<dim3(XBLKS + QKVN / 32, EMB / 32), 256>>>(x, W, ahi, bhi);

    qkv_gemm_mma<<<dim3(QKVN / GBN, TOK / GBM), 256, SM_TOT>>>(b);

    ktv_kernel<<<dim3(HEADS, 32), 128>>>();
    ktv_reduce<<<512, 256>>>();
    out_kernel<<<dim3(HEADS, 32), 128, OSM_TOT>>>(coarse, out);
}

// round 12
// speedup vs baseline: 6.4477x; 1.0300x over previous
#include <cuda_runtime.h>
#include <cuda_fp16.h>
#include <cstdint>

#define TOK   4096
#define EMB   512
#define QKVN  1536
#define HEADS 8
#define DH    64
#define SCALE 0.125f

#define HSTRIDE (TOK * DH)           // 262144
#define PSTRIDE (HEADS * TOK * DH)   // 2097152

#define KTV_SPLITS 16

// ---------------- scratch (device globals) ----------------
__device__ float g_qkv[3 * HEADS * TOK * DH];        // [part][h][n][d] (V part unused now)
__device__ float g_qsum[HEADS * DH];
__device__ float g_qsum_part[32 * HEADS * DH];       // [m_block][h*64+d]
__device__ float g_ktv[HEADS * DH * DH];
__device__ float g_ktv_part[KTV_SPLITS * HEADS * DH * DH];

__device__ __half g_a_hi[TOK * EMB];                 // A = x^T  [4096, 512]
__device__ __half g_b_hi[QKVN * EMB];                // B = W^T  [1536, 512]
__device__ __half g_kT[HEADS * DH * TOK];            // K^T fp16 [h][d][n]
__device__ __half g_vT[HEADS * DH * TOK];            // V^T fp16 [h][d][n]

// ---------------- helpers ----------------
__device__ __forceinline__ uint32_t smem_u32(const void* p) {
    uint32_t a;
    asm("{ .reg .u64 t; cvta.to.shared.u64 t, %1; cvt.u32.u64 %0, t; }" : "=r"(a) : "l"(p));
    return a;
}
__device__ __forceinline__ uint32_t lds32(uint32_t a) {
    uint32_t v;
    asm volatile("ld.shared.b32 %0, [%1];" : "=r"(v) : "r"(a));
    return v;
}
__device__ __forceinline__ void cp_async16(uint32_t saddr, const void* gaddr) {
    asm volatile("cp.async.cg.shared.global [%0], [%1], 16;" :: "r"(saddr), "l"(gaddr));
}
__device__ __forceinline__ void cp_commit() { asm volatile("cp.async.commit_group;"); }
__device__ __forceinline__ void cp_wait1()  { asm volatile("cp.async.wait_group 1;"); }
__device__ __forceinline__ void cp_wait0()  { asm volatile("cp.async.wait_group 0;"); }

__device__ __forceinline__ void mma_f16(float& c0, float& c1, float& c2, float& c3,
                                        uint32_t a0, uint32_t a1, uint32_t a2, uint32_t a3,
                                        uint32_t b0, uint32_t b1) {
    asm volatile(
        "mma.sync.aligned.m16n8k16.row.col.f32.f16.f16.f32 "
        "{%0,%1,%2,%3}, {%4,%5,%6,%7}, {%8,%9}, {%0,%1,%2,%3};"
        : "+f"(c0), "+f"(c1), "+f"(c2), "+f"(c3)
        : "r"(a0), "r"(a1), "r"(a2), "r"(a3), "r"(b0), "r"(b1));
}

// packed fp32x2 (Blackwell FFMA2 path, exact fp32 semantics)
__device__ __forceinline__ unsigned long long dup2(float x) {
    unsigned long long r;
    asm("mov.b64 %0, {%1, %1};" : "=l"(r) : "f"(x));
    return r;
}
__device__ __forceinline__ unsigned long long fma2(unsigned long long a,
                                                   unsigned long long b,
                                                   unsigned long long c) {
    unsigned long long d;
    asm("fma.rn.f32x2 %0, %1, %2, %3;" : "=l"(d) : "l"(a), "l"(b), "l"(c));
    return d;
}
__device__ __forceinline__ void unpack2(unsigned long long v, float& x, float& y) {
    asm("mov.b64 {%0, %1}, %2;" : "=f"(x), "=f"(y) : "l"(v));
}
__device__ __forceinline__ void lds_v2u64(uint32_t addr, unsigned long long& a,
                                          unsigned long long& b) {
    asm volatile("ld.shared.v2.u64 {%0, %1}, [%2];" : "=l"(a), "=l"(b) : "r"(addr));
}

// ---------------------------------------------------------------------------
// Merged pre-pass: transpose x->ahi and W->bhi, half2 stores
// ---------------------------------------------------------------------------
#define XBLKS (TOK / 32)      // 128
__global__ __launch_bounds__(256) void conv_transpose2(const float* __restrict__ x,
                                                       const float* __restrict__ W,
                                                       __half* __restrict__ ahi,
                                                       __half* __restrict__ bhi) {
    __shared__ float tile[32][33];
    int tid = threadIdx.x;
    int tx = tid & 31, ty = tid >> 5;
    int bx = blockIdx.x;
    const float* src;
    __half* dst;
    int Mcols, m0;
    if (bx < XBLKS) { src = x; dst = ahi; Mcols = TOK;  m0 = bx * 32; }
    else            { src = W; dst = bhi; Mcols = QKVN; m0 = (bx - XBLKS) * 32; }
    int k0 = blockIdx.y * 32;
#pragma unroll
    for (int j = 0; j < 4; j++)
        tile[ty + j * 8][tx] = src[(size_t)(k0 + ty + j * 8) * Mcols + m0 + tx];
    __syncthreads();
    int r2 = tid >> 4;
    int c2 = tid & 15;
#pragma unroll
    for (int j = 0; j < 2; j++) {
        int row = r2 + j * 16;
        int m = m0 + row;
        __half2 v = __floats2half2_rn(tile[c2 * 2][row], tile[c2 * 2 + 1][row]);
        *reinterpret_cast<__half2*>(&dst[(size_t)m * EMB + k0 + c2 * 2]) = v;
    }
}

// ---------------------------------------------------------------------------
// mma.sync QKV GEMM; epilogue: Q,K fp32 scatter + K,V transposed fp16 emit
// ---------------------------------------------------------------------------
#define GBM 128
#define GBN 128
#define GBK 32
#define ROWB   80
#define TILE_B (128 * ROWB)
#define T_AHI  0
#define T_BHI  (1 * TILE_B)
#define STG_B  (2 * TILE_B)
#define SM_BIAS (2 * STG_B)
#define SM_QS   (SM_BIAS + 512)
#define SM_TOT  (SM_QS + 1024)

__global__ void __launch_bounds__(256, 2) qkv_gemm_mma(const float* __restrict__ bias) {
    extern __shared__ char smem[];
    const uint32_t sb = smem_u32(smem);
    const int tid  = threadIdx.x;
    const int wid  = tid >> 5;
    const int lane = tid & 31;
    const int g    = lane >> 2;
    const int tg   = lane & 3;
    const int wm   = wid >> 2;
    const int wn   = wid & 3;
    const int o0   = blockIdx.x * GBN;
    const int m0   = blockIdx.y * GBM;

    if (tid < 128) *reinterpret_cast<float*>(smem + SM_BIAS + tid * 4) = bias[o0 + tid];

    const __half* srcs[2] = {
        &g_a_hi[(size_t)m0 * EMB], &g_b_hi[(size_t)o0 * EMB]};

    auto issue = [&](int chunk) {
        const int kt = chunk * GBK;
        const uint32_t stage = sb + (chunk & 1) * STG_B;
#pragma unroll
        for (int t = 0; t < 2; t++) {
            const __half* gp = srcs[t] + kt;
            const uint32_t tb = stage + t * TILE_B;
#pragma unroll
            for (int i = 0; i < 2; i++) {
                int lin = tid + i * 256;
                int row = lin >> 2;
                int seg = lin & 3;
                cp_async16(tb + row * ROWB + seg * 16, gp + (size_t)row * EMB + seg * 8);
            }
        }
        cp_commit();
    };

    float acc[4][4][4];
#pragma unroll
    for (int i = 0; i < 4; i++)
#pragma unroll
        for (int j = 0; j < 4; j++)
#pragma unroll
            for (int c = 0; c < 4; c++) acc[i][j][c] = 0.f;

    issue(0);

    const uint32_t aRow0 = wm * 64 + g;
    const uint32_t bRow0 = wn * 32 + g;

    for (int chunk = 0; chunk < EMB / GBK; ++chunk) {
        if (chunk + 1 < EMB / GBK) { issue(chunk + 1); cp_wait1(); }
        else                       { cp_wait0(); }
        __syncthreads();

        const uint32_t stage = sb + (chunk & 1) * STG_B;

#pragma unroll
        for (int kk = 0; kk < 2; kk++) {
            const uint32_t klo = kk * 32 + tg * 4;

            uint32_t afr[4][4], bfr[4][2];
#pragma unroll
            for (int nt = 0; nt < 4; nt++) {
                uint32_t base = stage + (bRow0 + nt * 8) * ROWB + klo + T_BHI;
                bfr[nt][0] = lds32(base);
                bfr[nt][1] = lds32(base + 16);
            }
#pragma unroll
            for (int mt = 0; mt < 4; mt++) {
                uint32_t base = stage + (aRow0 + mt * 16) * ROWB + klo + T_AHI;
                afr[mt][0] = lds32(base);
                afr[mt][1] = lds32(base + 8 * ROWB);
                afr[mt][2] = lds32(base + 16);
                afr[mt][3] = lds32(base + 8 * ROWB + 16);
            }
#pragma unroll
            for (int mt = 0; mt < 4; mt++)
#pragma unroll
                for (int nt = 0; nt < 4; nt++)
                    mma_f16(acc[mt][nt][0], acc[mt][nt][1], acc[mt][nt][2], acc[mt][nt][3],
                            afr[mt][0], afr[mt][1], afr[mt][2], afr[mt][3],
                            bfr[nt][0], bfr[nt][1]);
        }
        __syncthreads();
    }

    const float* sbias = reinterpret_cast<const float*>(smem + SM_BIAS);
#pragma unroll
    for (int mt = 0; mt < 4; mt++) {
        const int m = m0 + wm * 64 + mt * 16 + g;
#pragma unroll
        for (int nt = 0; nt < 4; nt++) {
            const int off = wn * 32 + nt * 8 + 2 * tg;
            const int o = o0 + off;
            const int part = o >> 9;
            const int h = (o >> 6) & 7;
            const int d = o & 63;
            const float bv0 = sbias[off], bv1 = sbias[off + 1];
            const float v00 = acc[mt][nt][0] + bv0;
            const float v01 = acc[mt][nt][1] + bv1;
            const float v10 = acc[mt][nt][2] + bv0;
            const float v11 = acc[mt][nt][3] + bv1;
            if (part < 2) {
                // Q and K keep fp32 scatter (out reads Q; coarse reads K)
                float* base = &g_qkv[(size_t)part * PSTRIDE + (size_t)h * HSTRIDE];
                *reinterpret_cast<float2*>(&base[(size_t)m * DH + d]) = make_float2(v00, v01);
                *reinterpret_cast<float2*>(&base[(size_t)(m + 8) * DH + d]) = make_float2(v10, v11);
            }
            if (part >= 1) {
                // K (part 1) and V (part 2) also emit transposed fp16 [h][d][n]
                __half* dT = (part == 1 ? g_kT : g_vT) + (size_t)h * DH * TOK;
                dT[(size_t)(d + 0) * TOK + m]     = __float2half_rn(v00);
                dT[(size_t)(d + 1) * TOK + m]     = __float2half_rn(v01);
                dT[(size_t)(d + 0) * TOK + m + 8] = __float2half_rn(v10);
                dT[(size_t)(d + 1) * TOK + m + 8] = __float2half_rn(v11);
            }
        }
    }

    // fused qsum partial
    if (o0 < 512) {
        float* qs = reinterpret_cast<float*>(smem + SM_QS);
        float cs[8];
#pragma unroll
        for (int nt = 0; nt < 4; nt++)
#pragma unroll
            for (int j = 0; j < 2; j++) {
                const int off = wn * 32 + nt * 8 + 2 * tg + j;
                float s = 8.f * sbias[off];
#pragma unroll
                for (int mt = 0; mt < 4; mt++)
                    s += acc[mt][nt][j] + acc[mt][nt][j + 2];
                cs[nt * 2 + j] = s;
            }
#pragma unroll
        for (int i = 0; i < 8; i++) {
#pragma unroll
            for (int off = 4; off < 32; off <<= 1)
                cs[i] += __shfl_xor_sync(0xffffffffu, cs[i], off);
        }
        if (g == 0) {
#pragma unroll
            for (int nt = 0; nt < 4; nt++)
#pragma unroll
                for (int j = 0; j < 2; j++)
                    qs[wm * 128 + wn * 32 + nt * 8 + 2 * tg + j] = cs[nt * 2 + j];
        }
        __syncthreads();
        if (tid < 128)
            g_qsum_part[blockIdx.y * 512 + o0 + tid] = qs[tid] + qs[128 + tid];
    }
}

// ---------------------------------------------------------------------------
// KtV via mma.sync: per (head, 16 splits), D[64][64] += KT(64x256) * VT(64x256)^T
// Fragment load pattern identical to the proven qkv GEMM.
// ---------------------------------------------------------------------------
#define KT_ROWB 528                        // 264 halves; (row*132+tg) mod 32 conflict-free
#define KT_TILE (64 * KT_ROWB)             // 33792 B
#define KTV_SMEM (2 * KT_TILE)             // 67584 B

__global__ void __launch_bounds__(128) ktv_mma() {
    extern __shared__ char ksm[];
    const uint32_t sb = smem_u32(ksm);
    const int h = blockIdx.x;
    const int split = blockIdx.y;          // 0..15
    const int tid = threadIdx.x;
    const int lane = tid & 31;
    const int w = tid >> 5;                // 0..3
    const int grow = lane >> 2;
    const int tg = lane & 3;

    const __half* Ksrc = &g_kT[(size_t)h * DH * TOK + split * 256];
    const __half* Vsrc = &g_vT[(size_t)h * DH * TOK + split * 256];

    // load 64 rows x 256 halves (512 B) each for KT and VT: 2048 16B chunks / 128 thr
#pragma unroll
    for (int i = 0; i < 16; i++) {
        int lin = tid + i * 128;           // 0..2047
        int r = lin >> 5;
        int c = lin & 31;
        cp_async16(sb + r * KT_ROWB + c * 16, Ksrc + (size_t)r * TOK + c * 8);
        cp_async16(sb + KT_TILE + r * KT_ROWB + c * 16, Vsrc + (size_t)r * TOK + c * 8);
    }
    cp_commit();
    cp_wait0();
    __syncthreads();

    float acc[8][4];
#pragma unroll
    for (int nt = 0; nt < 8; nt++)
#pragma unroll
        for (int c = 0; c < 4; c++) acc[nt][c] = 0.f;

    const uint32_t aBase = sb + (w * 16 + grow) * KT_ROWB + tg * 4;
    const uint32_t bBase = sb + KT_TILE + grow * KT_ROWB + tg * 4;

#pragma unroll
    for (int kk = 0; kk < 16; kk++) {
        const uint32_t ko = kk * 32;
        uint32_t a0 = lds32(aBase + ko);
        uint32_t a1 = lds32(aBase + 8 * KT_ROWB + ko);
        uint32_t a2 = lds32(aBase + ko + 16);
        uint32_t a3 = lds32(aBase + 8 * KT_ROWB + ko + 16);
#pragma unroll
        for (int nt = 0; nt < 8; nt++) {
            uint32_t bb = bBase + nt * 8 * KT_ROWB + ko;
            uint32_t b0 = lds32(bb);
            uint32_t b1 = lds32(bb + 16);
            mma_f16(acc[nt][0], acc[nt][1], acc[nt][2], acc[nt][3],
                    a0, a1, a2, a3, b0, b1);
        }
    }

    float* dst = &g_ktv_part[(size_t)split * (HEADS * DH * DH) + (size_t)h * DH * DH];
    const int d1 = w * 16 + grow;
#pragma unroll
    for (int nt = 0; nt < 8; nt++) {
        const int d2 = nt * 8 + 2 * tg;
        *reinterpret_cast<float2*>(&dst[d1 * DH + d2]) = make_float2(acc[nt][0], acc[nt][1]);
        *reinterpret_cast<float2*>(&dst[(d1 + 8) * DH + d2]) = make_float2(acc[nt][2], acc[nt][3]);
    }
}

// ---------------------------------------------------------------------------
// ktv reduce (16 splits, 2 thr/output) + fused qsum reduce (32 m-blocks)
// ---------------------------------------------------------------------------
__global__ __launch_bounds__(256) void ktv_reduce() {
    int gt = blockIdx.x * 256 + threadIdx.x;   // 0 .. 65535
    int o  = gt >> 1;                          // 0..32767
    int p  = gt & 1;
    float s = 0.f;
#pragma unroll
    for (int j = 0; j < 8; j++)
        s += g_ktv_part[(size_t)(p * 8 + j) * (HEADS * DH * DH) + o];
    s += __shfl_xor_sync(0xffffffffu, s, 1);
    if (p == 0) g_ktv[o] = s;

    if (gt < 2048) {                           // qsum: 512 outputs x 4 threads, 32 splits
        int o2 = gt >> 2;
        int p2 = gt & 3;
        float q = 0.f;
#pragma unroll
        for (int j = 0; j < 8; j++)
            q += g_qsum_part[(p2 * 8 + j) * (HEADS * DH) + o2];
        q += __shfl_xor_sync(0xffffffffu, q, 1);
        q += __shfl_xor_sync(0xffffffffu, q, 2);
        if (p2 == 0) g_qsum[o2] = q;
    }
}

// ---------------------------------------------------------------------------
// out (unchanged): 1 row/thread, full-M broadcast sweep, f32x2
// ---------------------------------------------------------------------------
#define OQ_PAD 65
#define OSM_M   0
#define OSM_Q   16384
#define OSM_QS  (OSM_Q + 128 * OQ_PAD * 4)
#define OSM_TOT (OSM_QS + 256)

__global__ void __launch_bounds__(128, 1) out_kernel(float* __restrict__ coarse,
                                                     float* __restrict__ out) {
    extern __shared__ char osm[];
    float* sM  = reinterpret_cast<float*>(osm + OSM_M);
    float* sQ  = reinterpret_cast<float*>(osm + OSM_Q);
    float* sQs = reinterpret_cast<float*>(osm + OSM_QS);
    const uint32_t sMb = smem_u32(sM);
    const uint32_t sQb = smem_u32(sQ);

    int h = blockIdx.x;
    int nt = blockIdx.y;
    int tid = threadIdx.x;
    int n = nt * 128 + tid;

#pragma unroll
    for (int i = 0; i < 8; i++) {
        int lin = tid + i * 128;
        *reinterpret_cast<float4*>(&sM[lin * 4]) =
            *reinterpret_cast<const float4*>(&g_ktv[(size_t)h * DH * DH + lin * 4]);
    }
    if (tid < 64) sQs[tid] = g_qsum[h * 64 + tid];

    const float* Qg = &g_qkv[(size_t)h * HSTRIDE + (size_t)nt * 128 * DH];
#pragma unroll
    for (int i = 0; i < 16; i++) {
        int lin = tid + i * 128;
        int r = lin >> 4;
        int c = (lin & 15) * 4;
        float4 v = *reinterpret_cast<const float4*>(&Qg[(size_t)r * DH + c]);
        float* dq = &sQ[r * OQ_PAD + c];
        dq[0] = v.x; dq[1] = v.y; dq[2] = v.z; dq[3] = v.w;
    }
    __syncthreads();

    const float* Kr = &g_qkv[(size_t)1 * PSTRIDE + (size_t)h * HSTRIDE + (size_t)n * DH];
    float cacc = 0.f;
#pragma unroll
    for (int d4 = 0; d4 < 64; d4 += 4) {
        float4 k4 = *reinterpret_cast<const float4*>(&Kr[d4]);
        cacc += k4.x * sQs[d4] + k4.y * sQs[d4 + 1] + k4.z * sQs[d4 + 2] + k4.w * sQs[d4 + 3];
    }
    coarse[h * TOK + n] = cacc * SCALE;

    unsigned long long acc2[32];
#pragma unroll
    for (int i = 0; i < 32; i++) acc2[i] = 0ull;

    const uint32_t qrow = sQb + tid * (OQ_PAD * 4);
#pragma unroll 8
    for (int d1 = 0; d1 < 64; d1++) {
        unsigned long long qd = dup2(__uint_as_float(lds32(qrow + d1 * 4)));
        const uint32_t mrow = sMb + d1 * 256;
#pragma unroll
        for (int c = 0; c < 16; c++) {
            unsigned long long m0, m1;
            lds_v2u64(mrow + c * 16, m0, m1);
            acc2[c * 2]     = fma2(qd, m0, acc2[c * 2]);
            acc2[c * 2 + 1] = fma2(qd, m1, acc2[c * 2 + 1]);
        }
    }

    float* op = &out[((size_t)h * TOK + n) * DH];
#pragma unroll
    for (int c = 0; c < 16; c++) {
        float4 v;
        unpack2(acc2[c * 2], v.x, v.y);
        unpack2(acc2[c * 2 + 1], v.z, v.w);
        v.x *= SCALE; v.y *= SCALE; v.z *= SCALE; v.w *= SCALE;
        *reinterpret_cast<float4*>(&op[c * 4]) = v;
    }
}

// ---------------------------------------------------------------------------
extern "C" void kernel_launch(void* const* d_in, const int* in_sizes, int n_in,
                              void* d_out, int out_size) {
    const float* x = (const float*)d_in[0];   // [512, 4096]
    const float* W = (const float*)d_in[1];   // [512, 1536]
    const float* b = (const float*)d_in[2];   // [1536]

    float* coarse = (float*)d_out;
    float* out    = (float*)d_out + HEADS * TOK;

    __half *ahi, *bhi;
    cudaGetSymbolAddress((void**)&ahi, g_a_hi);
    cudaGetSymbolAddress((void**)&bhi, g_b_hi);

    cudaFuncSetAttribute(qkv_gemm_mma, cudaFuncAttributeMaxDynamicSharedMemorySize, SM_TOT);
    cudaFuncSetAttribute(ktv_mma, cudaFuncAttributeMaxDynamicSharedMemorySize, KTV_SMEM);
    cudaFuncSetAttribute(out_kernel, cudaFuncAttributeMaxDynamicSharedMemorySize, OSM_TOT);

    conv_transpose2<<<dim3(XBLKS + QKVN / 32, EMB / 32), 256>>>(x, W, ahi, bhi);

    qkv_gemm_mma<<<dim3(QKVN / GBN, TOK / GBM), 256, SM_TOT>>>(b);

    ktv_mma<<<dim3(HEADS, KTV_SPLITS), 128, KTV_SMEM>>>();
    ktv_reduce<<<256, 256>>>();
    out_kernel<<<dim3(HEADS, 32), 128, OSM_TOT>>>(coarse, out);
}